// round 15
// baseline (speedup 1.0000x reference)
#include <cuda_runtime.h>
#include <cuda_bf16.h>
#include <cuda_pipeline.h>
#include <mma.h>
#include <cstdint>

using namespace nvcuda;

// InfoNCELoss: int8 WMMA tensor-core LSE GEMM + cp.async pipeline + dedup.
// R15 = R14 GEMM core +
//  (a) multiplicity-weighted reduction: sum over UNIQUE positions (coalesced,
//      ~3224 logf) weighted by duplicate count, instead of the random
//      g_rank[pa[p]] gather that made reduce_final 17.2us,
//  (b) dedup merged into the normalize launch as an extra block (independent
//      inputs -> runs concurrently; removes ~5us serialized single-block time).
//
// loss = mean_p[ LSE_j(dot(e_a,e_j)/T) - dot(e_a,e_t)/T ],  e row-normalized.
// Fixed-shift LSE: C = 1/T (self-sim logit == C):
//   loss = C + (sum_pos mult*log es(pos) - C * sum_p posdot) / N_POS.
// int8 per-row quantized GEMM (exact s32 accum); pos_sim/neg_sim/pos_logit on
// an exact fp32 pair-dot path. Reductions write-once or int-atomic ->
// deterministic.

#define N_EMB 8192
#define D     512
#define N_POS 4096
#define N_NEG 16384
#define INV_T   14.2857142857142857f
#define INV_T_D 14.285714285714285714

// ---- GEMM tiling ----
#define BM 128
#define BN 128
#define BK 128
#define NKS (D / BK)            // 4 k-stages
#define NMT (N_POS / BM)        // 32 (upper bound; real = ceil(count/128))
#define NNT (N_EMB / BN)        // 64
#define KSTR 144
#define STAGES 3
#define STAGE_A (BM * KSTR)                     // 18432 B
#define STAGE_BYTES (2 * STAGE_A)               // 36864 B (A + B)
#define SM_AROW_OFF (STAGES * STAGE_BYTES)      // 110592
#define SM_RED_OFF  (SM_AROW_OFF + BM * 4)      // 111104
#define SM_SA_OFF   (SM_RED_OFF + BM * 2 * 4)   // 112128
#define SM_SB_OFF   (SM_SA_OFF + BM * 4)        // 112640
#define SMEM_TOTAL  (SM_SB_OFF + BN * 4)        // 113152 B -> 2 CTAs/SM

// ---- device scratch ----
__device__ float          g_enorm[N_EMB * D];
__device__ signed char    g_eq[N_EMB * D];
__device__ float          g_rscale[N_EMB];
__device__ float          g_posdot[N_POS];
__device__ float          g_negdot[N_NEG];
__device__ float          g_part[NNT][N_POS];
__device__ double         g_red[48][3];
__device__ int            g_uniq[N_POS];      // compacted unique anchor rows
__device__ int            g_mult_pos[N_POS];  // duplicate count per position
__device__ int            g_count[1];
__device__ int            g_ctr;              // reduce ticket

static __device__ __forceinline__ float warp_sum_f(float v) {
#pragma unroll
    for (int o = 16; o; o >>= 1) v += __shfl_xor_sync(0xffffffffu, v, o);
    return v;
}
static __device__ __forceinline__ float warp_max_f(float v) {
#pragma unroll
    for (int o = 16; o; o >>= 1) v = fmaxf(v, __shfl_xor_sync(0xffffffffu, v, o));
    return v;
}
static __device__ __forceinline__ double warp_sum_d(double v) {
#pragma unroll
    for (int o = 16; o; o >>= 1) v += __shfl_xor_sync(0xffffffffu, v, o);
    return v;
}

// ---------------------------------------------------------------------------
// 1) Normalize rows (blocks 0..N_EMB-1) + dedup (block N_EMB). 128 threads.
// ---------------------------------------------------------------------------
__global__ void normalize_kernel(const float* __restrict__ emb,
                                 const int* __restrict__ pa) {
    __shared__ int counts[N_EMB];     // dedup branch only (32 KB)
    __shared__ int tsum[128];
    __shared__ int wsum[4];
    __shared__ float ws[4], wm[4];

    const int t = threadIdx.x;        // 0..127

    if (blockIdx.x == N_EMB) {
        // ---- dedup + multiplicity (counts via int atomics: deterministic) --
        if (t == 0) g_ctr = 0;
#pragma unroll
        for (int i = 0; i < N_EMB / 128; i++) counts[t + 128 * i] = 0;
        __syncthreads();
#pragma unroll
        for (int i = 0; i < N_POS / 128; i++)
            atomicAdd(&counts[pa[t + 128 * i]], 1);
        __syncthreads();

        const int base = t * (N_EMB / 128);   // 64 rows per thread
        int s = 0;
        for (int i = 0; i < 64; i++) s += (counts[base + i] > 0);
        tsum[t] = s;
        __syncthreads();

        const int lane = t & 31, w = t >> 5;
        int v = tsum[t], inc = v;
#pragma unroll
        for (int o = 1; o < 32; o <<= 1) {
            int u = __shfl_up_sync(0xffffffffu, inc, o);
            if (lane >= o) inc += u;
        }
        if (lane == 31) wsum[w] = inc;
        __syncthreads();
        if (t == 0) {
            int run = 0;
#pragma unroll
            for (int i = 0; i < 4; i++) { int x = wsum[i]; wsum[i] = run; run += x; }
            g_count[0] = run;
        }
        __syncthreads();
        int pos = wsum[w] + inc - v;      // exclusive prefix
        for (int i = 0; i < 64; i++) {
            const int c = counts[base + i];
            if (c > 0) {
                g_uniq[pos] = base + i;
                g_mult_pos[pos] = c;
                pos++;
            }
        }
        return;
    }

    // ---- normalize branch ----
    const int row = blockIdx.x;
    float4 a = reinterpret_cast<const float4*>(emb + (size_t)row * D)[t];
    float ss = a.x * a.x + a.y * a.y + a.z * a.z + a.w * a.w;
    float mx = fmaxf(fmaxf(fabsf(a.x), fabsf(a.y)), fmaxf(fabsf(a.z), fabsf(a.w)));
    ss = warp_sum_f(ss);
    mx = warp_max_f(mx);
    if ((t & 31) == 0) { ws[t >> 5] = ss; wm[t >> 5] = mx; }
    __syncthreads();
    float inv = 1.0f / fmaxf(sqrtf(ws[0] + ws[1] + ws[2] + ws[3]), 1e-8f);
    float amax = fmaxf(fmaxf(wm[0], wm[1]), fmaxf(wm[2], wm[3])) * inv;
    float4 o4 = make_float4(a.x * inv, a.y * inv, a.z * inv, a.w * inv);
    reinterpret_cast<float4*>(g_enorm + (size_t)row * D)[t] = o4;

    const float qs = 127.0f / fmaxf(amax, 1e-12f);
    char4 q = make_char4((signed char)__float2int_rn(o4.x * qs),
                         (signed char)__float2int_rn(o4.y * qs),
                         (signed char)__float2int_rn(o4.z * qs),
                         (signed char)__float2int_rn(o4.w * qs));
    reinterpret_cast<char4*>(g_eq + (size_t)row * D)[t] = q;
    if (t == 0) g_rscale[row] = fmaxf(amax, 1e-12f) * (1.0f / 127.0f);
}

// ---------------------------------------------------------------------------
// 2+3) Fused launch: GEMM tiles (x < NMT) + pair-dot blocks (x >= NMT).
// ---------------------------------------------------------------------------
__global__ __launch_bounds__(256, 2) void lse_gemm_fused(
        const int* __restrict__ pa, const int* __restrict__ pt,
        const int* __restrict__ na, const int* __restrict__ nt) {
    const int tid = threadIdx.x;
    const int wid = tid >> 5;
    const int lane = tid & 31;

    if (blockIdx.x >= NMT) {
        const int w0 = ((blockIdx.x - NMT) * NNT + blockIdx.y) * 8 + wid;  // 0..1023
#pragma unroll
        for (int i = 0; i < 20; i++) {
            const int w = w0 + 1024 * i;
            int ai, ti;
            bool is_pos;
            if (w < N_POS) { ai = pa[w]; ti = pt[w]; is_pos = true; }
            else { ai = na[w - N_POS]; ti = nt[w - N_POS]; is_pos = false; }
            const float4* va = reinterpret_cast<const float4*>(g_enorm + (size_t)ai * D);
            const float4* vb = reinterpret_cast<const float4*>(g_enorm + (size_t)ti * D);
            float s = 0.f;
#pragma unroll
            for (int c = 0; c < 4; c++) {
                float4 x = va[lane + 32 * c];
                float4 y = vb[lane + 32 * c];
                s += x.x * y.x + x.y * y.y + x.z * y.z + x.w * y.w;
            }
            s = warp_sum_f(s);
            if (lane == 0) {
                if (is_pos) g_posdot[w] = s;
                else        g_negdot[w - N_POS] = s;
            }
        }
        return;
    }

    const int p0 = blockIdx.x * BM;
    const int cnt = g_count[0];
    if (p0 >= cnt) return;

    extern __shared__ __align__(16) char sm[];
    int*   arow = reinterpret_cast<int*>(sm + SM_AROW_OFF);
    float* red  = reinterpret_cast<float*>(sm + SM_RED_OFF);
    float* sa_s = reinterpret_cast<float*>(sm + SM_SA_OFF);
    float* sb_s = reinterpret_cast<float*>(sm + SM_SB_OFF);

    const int j0 = blockIdx.y * BN;
    const int warp_m = wid & 3;
    const int warp_n = wid >> 2;

    if (tid < BM) {
        const int idx = p0 + tid;
        const int r = g_uniq[idx < cnt ? idx : 0];
        arow[tid] = r;
        sa_s[tid] = g_rscale[r];
        sb_s[tid] = g_rscale[j0 + tid];
    }
    __syncthreads();

    const signed char* asrc[4];
    const signed char* bsrc[4];
    int soff[4];
#pragma unroll
    for (int i = 0; i < 4; i++) {
        int f = tid + 256 * i;
        int r = f >> 3, kc = (f & 7) * 16;
        asrc[i] = g_eq + (size_t)arow[r] * D + kc;
        bsrc[i] = g_eq + (size_t)(j0 + r) * D + kc;
        soff[i] = r * KSTR + kc;
    }

    auto issue = [&](int kt) {
        const int buf = kt % STAGES;
        const int ko = kt * BK;
        char* da = sm + buf * STAGE_BYTES;
        char* db = da + STAGE_A;
#pragma unroll
        for (int i = 0; i < 4; i++) {
            __pipeline_memcpy_async(da + soff[i], asrc[i] + ko, 16);
            __pipeline_memcpy_async(db + soff[i], bsrc[i] + ko, 16);
        }
        __pipeline_commit();
    };

    wmma::fragment<wmma::accumulator, 16, 16, 16, int> acc[2][4];
#pragma unroll
    for (int mt = 0; mt < 2; mt++)
#pragma unroll
        for (int nt = 0; nt < 4; nt++) wmma::fill_fragment(acc[mt][nt], 0);

    issue(0);
    issue(1);

    for (int kt = 0; kt < NKS; kt++) {
        const int buf = kt % STAGES;
        __pipeline_wait_prior(STAGES - 2);
        __syncthreads();

        if (kt + STAGES - 1 < NKS) issue(kt + STAGES - 1);
        else __pipeline_commit();

        const signed char* A = reinterpret_cast<const signed char*>(sm + buf * STAGE_BYTES);
        const signed char* B = reinterpret_cast<const signed char*>(sm + buf * STAGE_BYTES + STAGE_A);

        wmma::fragment<wmma::matrix_b, 16, 16, 16, signed char, wmma::col_major> bf[2][4];
        wmma::fragment<wmma::matrix_a, 16, 16, 16, signed char, wmma::row_major> af[2][2];
#pragma unroll
        for (int nt = 0; nt < 4; nt++)
            wmma::load_matrix_sync(bf[0][nt], B + (warp_n * 64 + nt * 16) * KSTR, KSTR);
#pragma unroll
        for (int mt = 0; mt < 2; mt++)
            wmma::load_matrix_sync(af[0][mt], A + (warp_m * 32 + mt * 16) * KSTR, KSTR);

#pragma unroll
        for (int ks = 0; ks < BK; ks += 16) {
            const int cur = (ks >> 4) & 1, nxt = cur ^ 1;
            if (ks + 16 < BK) {
#pragma unroll
                for (int nt = 0; nt < 4; nt++)
                    wmma::load_matrix_sync(bf[nxt][nt],
                        B + (warp_n * 64 + nt * 16) * KSTR + ks + 16, KSTR);
#pragma unroll
                for (int mt = 0; mt < 2; mt++)
                    wmma::load_matrix_sync(af[nxt][mt],
                        A + (warp_m * 32 + mt * 16) * KSTR + ks + 16, KSTR);
            }
#pragma unroll
            for (int mt = 0; mt < 2; mt++)
#pragma unroll
                for (int nt = 0; nt < 4; nt++)
                    wmma::mma_sync(acc[mt][nt], af[cur][mt], bf[cur][nt], acc[mt][nt]);
        }
    }
    __syncthreads();

    int* scr = reinterpret_cast<int*>(sm) + wid * (16 * 20);
    const int row = lane >> 1, half = lane & 1;
#pragma unroll
    for (int mt = 0; mt < 2; mt++) {
        float rs = 0.f;
        const float sa_t = sa_s[warp_m * 32 + mt * 16 + row] * INV_T;
#pragma unroll
        for (int nt = 0; nt < 4; nt++) {
            __syncwarp();
            wmma::store_matrix_sync(scr, acc[mt][nt], 20, wmma::mem_row_major);
            __syncwarp();
            const int* rp = scr + row * 20 + half * 8;
            const int cb = warp_n * 64 + nt * 16 + half * 8;
#pragma unroll
            for (int i = 0; i < 8; i++) {
                float dv = (float)rp[i] * sb_s[cb + i];
                rs += __expf(fmaf(dv, sa_t, -INV_T));
            }
        }
        rs += __shfl_xor_sync(0xffffffffu, rs, 1);
        if (half == 0)
            red[(warp_m * 32 + mt * 16 + row) * 2 + warp_n] = rs;
    }
    __syncthreads();
    if (tid < BM)
        g_part[blockIdx.y][p0 + tid] = red[tid * 2 + 0] + red[tid * 2 + 1];
}

// ---------------------------------------------------------------------------
// 4) Reduce + final. Blocks 0..15: unique-position LSE (coalesced) weighted
//    by multiplicity + posdot sums. Blocks 16..47: neg sums. Ticket finishes.
// ---------------------------------------------------------------------------
__global__ void reduce_final_kernel(float* __restrict__ out, int out_size) {
    const int b = blockIdx.x, t = threadIdx.x;
    double v0 = 0.0, v1 = 0.0, v2 = 0.0;
    if (b < 16) {
        const int idx = b * 256 + t;
        if (idx < g_count[0]) {
            float es = 0.f;
#pragma unroll
            for (int c = 0; c < NNT; c++) es += g_part[c][idx];   // coalesced
            v0 = (double)g_mult_pos[idx] * (double)logf(es);
        }
        v1 = (double)g_posdot[idx];
    } else {
        const int q = (b - 16) * 512 + t;
        v2 = (double)g_negdot[q] + (double)g_negdot[q + 256];
    }
    v0 = warp_sum_d(v0); v1 = warp_sum_d(v1); v2 = warp_sum_d(v2);
    __shared__ double sh[3][8];
    __shared__ bool is_last;
    if ((t & 31) == 0) { sh[0][t >> 5] = v0; sh[1][t >> 5] = v1; sh[2][t >> 5] = v2; }
    __syncthreads();
    if (t == 0) {
        double a = 0, bb = 0, c = 0;
#pragma unroll
        for (int i = 0; i < 8; i++) { a += sh[0][i]; bb += sh[1][i]; c += sh[2][i]; }
        g_red[b][0] = a; g_red[b][1] = bb; g_red[b][2] = c;
        __threadfence();
        is_last = (atomicAdd(&g_ctr, 1) == 47);
    }
    __syncthreads();
    if (is_last) {
        if (t == 0) {
            volatile double* gr = &g_red[0][0];
            double L0 = 0, P = 0, Ng = 0;
            for (int i = 0; i < 48; i++) {
                L0 += gr[i * 3 + 0]; P += gr[i * 3 + 1]; Ng += gr[i * 3 + 2];
            }
            out[0] = (float)((L0 - INV_T_D * P) / N_POS + INV_T_D);
            out[1] = (float)(P / N_POS);
            out[2] = (float)(Ng / N_NEG);
        }
        for (int i = 3 + t; i < out_size; i += 256) out[i] = 0.f;
    }
}

// ---------------------------------------------------------------------------
extern "C" void kernel_launch(void* const* d_in, const int* in_sizes, int n_in,
                              void* d_out, int out_size) {
    const float* emb = (const float*)d_in[0];
    const int* pa = (const int*)d_in[1];
    const int* pt = (const int*)d_in[2];
    const int* na = (const int*)d_in[3];
    const int* nt = (const int*)d_in[4];
    float* out = (float*)d_out;
    (void)in_sizes; (void)n_in;

    cudaFuncSetAttribute(lse_gemm_fused,
                         cudaFuncAttributeMaxDynamicSharedMemorySize, SMEM_TOTAL);

    normalize_kernel<<<N_EMB + 1, 128>>>(emb, pa);   // +1 block = dedup

    dim3 grid(NMT + 2, NNT);   // +2 block-columns = 128 pair-dot blocks
    lse_gemm_fused<<<grid, 256, SMEM_TOTAL>>>(pa, pt, na, nt);

    reduce_final_kernel<<<48, 256>>>(out, out_size);
}

// round 16
// speedup vs baseline: 1.0756x; 1.0756x over previous
#include <cuda_runtime.h>
#include <cuda_bf16.h>
#include <cuda_pipeline.h>
#include <mma.h>
#include <cstdint>

using namespace nvcuda;

// InfoNCELoss: int8 WMMA tensor-core LSE GEMM + cp.async pipeline + dedup.
// R16 = R14 structure (standalone dedup: the R15 merge put a 32KB static smem
// array on ALL 8193 normalize blocks -> occupancy crash, normalize 8->26us)
//  + R15's multiplicity-weighted reduction kept (coalesced unique-position
//    reads, ~3224 logf, no random gather — reduce_final was 17.2us in R14).
//
// loss = mean_p[ LSE_j(dot(e_a,e_j)/T) - dot(e_a,e_t)/T ],  e row-normalized.
// Fixed-shift LSE: C = 1/T (self-sim logit == C):
//   loss = C + (sum_pos mult*log es(pos) - C * sum_p posdot) / N_POS.
// int8 per-row quantized GEMM (exact s32 accum); pos_sim/neg_sim/pos_logit on
// an exact fp32 pair-dot path. Reductions write-once or int-atomic ->
// deterministic.

#define N_EMB 8192
#define D     512
#define N_POS 4096
#define N_NEG 16384
#define INV_T   14.2857142857142857f
#define INV_T_D 14.285714285714285714

// ---- GEMM tiling ----
#define BM 128
#define BN 128
#define BK 128
#define NKS (D / BK)            // 4 k-stages
#define NMT (N_POS / BM)        // 32 (upper bound; real = ceil(count/128))
#define NNT (N_EMB / BN)        // 64
#define KSTR 144
#define STAGES 3
#define STAGE_A (BM * KSTR)                     // 18432 B
#define STAGE_BYTES (2 * STAGE_A)               // 36864 B (A + B)
#define SM_AROW_OFF (STAGES * STAGE_BYTES)      // 110592
#define SM_RED_OFF  (SM_AROW_OFF + BM * 4)      // 111104
#define SM_SA_OFF   (SM_RED_OFF + BM * 2 * 4)   // 112128
#define SM_SB_OFF   (SM_SA_OFF + BM * 4)        // 112640
#define SMEM_TOTAL  (SM_SB_OFF + BN * 4)        // 113152 B -> 2 CTAs/SM

// ---- device scratch ----
__device__ float          g_enorm[N_EMB * D];
__device__ signed char    g_eq[N_EMB * D];
__device__ float          g_rscale[N_EMB];
__device__ float          g_posdot[N_POS];
__device__ float          g_negdot[N_NEG];
__device__ float          g_part[NNT][N_POS];
__device__ double         g_red[48][3];
__device__ int            g_uniq[N_POS];      // compacted unique anchor rows
__device__ int            g_mult_pos[N_POS];  // duplicate count per position
__device__ int            g_count[1];
__device__ int            g_ctr;              // reduce ticket

static __device__ __forceinline__ float warp_sum_f(float v) {
#pragma unroll
    for (int o = 16; o; o >>= 1) v += __shfl_xor_sync(0xffffffffu, v, o);
    return v;
}
static __device__ __forceinline__ float warp_max_f(float v) {
#pragma unroll
    for (int o = 16; o; o >>= 1) v = fmaxf(v, __shfl_xor_sync(0xffffffffu, v, o));
    return v;
}
static __device__ __forceinline__ double warp_sum_d(double v) {
#pragma unroll
    for (int o = 16; o; o >>= 1) v += __shfl_xor_sync(0xffffffffu, v, o);
    return v;
}

// ---------------------------------------------------------------------------
// 0) Anchor dedup + multiplicity. One block, 1024 threads (32KB smem paid
//    by this single block only).
// ---------------------------------------------------------------------------
__global__ __launch_bounds__(1024) void dedup_kernel(const int* __restrict__ pa) {
    __shared__ int counts[N_EMB];
    __shared__ int tsum[1024];
    __shared__ int wsum[32];
    const int t = threadIdx.x;

    if (t == 0) g_ctr = 0;    // reset reduce ticket (stream-ordered)
#pragma unroll
    for (int i = 0; i < N_EMB / 1024; i++) counts[t + 1024 * i] = 0;
    __syncthreads();
#pragma unroll
    for (int i = 0; i < N_POS / 1024; i++)
        atomicAdd(&counts[pa[t + 1024 * i]], 1);
    __syncthreads();

    const int base = t * (N_EMB / 1024);   // 8 rows per thread
    int s = 0;
#pragma unroll
    for (int i = 0; i < 8; i++) s += (counts[base + i] > 0);
    tsum[t] = s;
    __syncthreads();

    const int lane = t & 31, w = t >> 5;
    int v = tsum[t], inc = v;
#pragma unroll
    for (int o = 1; o < 32; o <<= 1) {
        int u = __shfl_up_sync(0xffffffffu, inc, o);
        if (lane >= o) inc += u;
    }
    if (lane == 31) wsum[w] = inc;
    __syncthreads();
    if (w == 0) {
        int x = (lane < 32) ? wsum[lane] : 0;
        int xi = x;
#pragma unroll
        for (int o = 1; o < 32; o <<= 1) {
            int u = __shfl_up_sync(0xffffffffu, xi, o);
            if (lane >= o) xi += u;
        }
        wsum[lane] = xi - x;
    }
    __syncthreads();
    int pos = wsum[w] + inc - v;   // exclusive prefix for this thread

#pragma unroll
    for (int i = 0; i < 8; i++) {
        const int c = counts[base + i];
        if (c > 0) {
            g_uniq[pos] = base + i;
            g_mult_pos[pos] = c;
            pos++;
        }
    }
    if (t == 1023) g_count[0] = pos;
}

// ---------------------------------------------------------------------------
// 1) Normalize rows; emit fp32 (exact pair dots) + int8 per-row-scaled (MMA).
// ---------------------------------------------------------------------------
__global__ void normalize_kernel(const float* __restrict__ emb) {
    const int row = blockIdx.x;
    const int t = threadIdx.x;  // 0..127
    float4 a = reinterpret_cast<const float4*>(emb + (size_t)row * D)[t];
    float ss = a.x * a.x + a.y * a.y + a.z * a.z + a.w * a.w;
    float mx = fmaxf(fmaxf(fabsf(a.x), fabsf(a.y)), fmaxf(fabsf(a.z), fabsf(a.w)));
    ss = warp_sum_f(ss);
    mx = warp_max_f(mx);
    __shared__ float ws[4], wm[4];
    if ((t & 31) == 0) { ws[t >> 5] = ss; wm[t >> 5] = mx; }
    __syncthreads();
    float inv = 1.0f / fmaxf(sqrtf(ws[0] + ws[1] + ws[2] + ws[3]), 1e-8f);
    float amax = fmaxf(fmaxf(wm[0], wm[1]), fmaxf(wm[2], wm[3])) * inv;
    float4 o4 = make_float4(a.x * inv, a.y * inv, a.z * inv, a.w * inv);
    reinterpret_cast<float4*>(g_enorm + (size_t)row * D)[t] = o4;

    const float qs = 127.0f / fmaxf(amax, 1e-12f);
    char4 q = make_char4((signed char)__float2int_rn(o4.x * qs),
                         (signed char)__float2int_rn(o4.y * qs),
                         (signed char)__float2int_rn(o4.z * qs),
                         (signed char)__float2int_rn(o4.w * qs));
    reinterpret_cast<char4*>(g_eq + (size_t)row * D)[t] = q;
    if (t == 0) g_rscale[row] = fmaxf(amax, 1e-12f) * (1.0f / 127.0f);
}

// ---------------------------------------------------------------------------
// 2+3) Fused launch: GEMM tiles (x < NMT) + pair-dot blocks (x >= NMT).
// ---------------------------------------------------------------------------
__global__ __launch_bounds__(256, 2) void lse_gemm_fused(
        const int* __restrict__ pa, const int* __restrict__ pt,
        const int* __restrict__ na, const int* __restrict__ nt) {
    const int tid = threadIdx.x;
    const int wid = tid >> 5;
    const int lane = tid & 31;

    if (blockIdx.x >= NMT) {
        const int w0 = ((blockIdx.x - NMT) * NNT + blockIdx.y) * 8 + wid;  // 0..1023
#pragma unroll
        for (int i = 0; i < 20; i++) {
            const int w = w0 + 1024 * i;
            int ai, ti;
            bool is_pos;
            if (w < N_POS) { ai = pa[w]; ti = pt[w]; is_pos = true; }
            else { ai = na[w - N_POS]; ti = nt[w - N_POS]; is_pos = false; }
            const float4* va = reinterpret_cast<const float4*>(g_enorm + (size_t)ai * D);
            const float4* vb = reinterpret_cast<const float4*>(g_enorm + (size_t)ti * D);
            float s = 0.f;
#pragma unroll
            for (int c = 0; c < 4; c++) {
                float4 x = va[lane + 32 * c];
                float4 y = vb[lane + 32 * c];
                s += x.x * y.x + x.y * y.y + x.z * y.z + x.w * y.w;
            }
            s = warp_sum_f(s);
            if (lane == 0) {
                if (is_pos) g_posdot[w] = s;
                else        g_negdot[w - N_POS] = s;
            }
        }
        return;
    }

    const int p0 = blockIdx.x * BM;
    const int cnt = g_count[0];
    if (p0 >= cnt) return;

    extern __shared__ __align__(16) char sm[];
    int*   arow = reinterpret_cast<int*>(sm + SM_AROW_OFF);
    float* red  = reinterpret_cast<float*>(sm + SM_RED_OFF);
    float* sa_s = reinterpret_cast<float*>(sm + SM_SA_OFF);
    float* sb_s = reinterpret_cast<float*>(sm + SM_SB_OFF);

    const int j0 = blockIdx.y * BN;
    const int warp_m = wid & 3;
    const int warp_n = wid >> 2;

    if (tid < BM) {
        const int idx = p0 + tid;
        const int r = g_uniq[idx < cnt ? idx : 0];
        arow[tid] = r;
        sa_s[tid] = g_rscale[r];
        sb_s[tid] = g_rscale[j0 + tid];
    }
    __syncthreads();

    const signed char* asrc[4];
    const signed char* bsrc[4];
    int soff[4];
#pragma unroll
    for (int i = 0; i < 4; i++) {
        int f = tid + 256 * i;
        int r = f >> 3, kc = (f & 7) * 16;
        asrc[i] = g_eq + (size_t)arow[r] * D + kc;
        bsrc[i] = g_eq + (size_t)(j0 + r) * D + kc;
        soff[i] = r * KSTR + kc;
    }

    auto issue = [&](int kt) {
        const int buf = kt % STAGES;
        const int ko = kt * BK;
        char* da = sm + buf * STAGE_BYTES;
        char* db = da + STAGE_A;
#pragma unroll
        for (int i = 0; i < 4; i++) {
            __pipeline_memcpy_async(da + soff[i], asrc[i] + ko, 16);
            __pipeline_memcpy_async(db + soff[i], bsrc[i] + ko, 16);
        }
        __pipeline_commit();
    };

    wmma::fragment<wmma::accumulator, 16, 16, 16, int> acc[2][4];
#pragma unroll
    for (int mt = 0; mt < 2; mt++)
#pragma unroll
        for (int nt = 0; nt < 4; nt++) wmma::fill_fragment(acc[mt][nt], 0);

    issue(0);
    issue(1);

    for (int kt = 0; kt < NKS; kt++) {
        const int buf = kt % STAGES;
        __pipeline_wait_prior(STAGES - 2);
        __syncthreads();

        if (kt + STAGES - 1 < NKS) issue(kt + STAGES - 1);
        else __pipeline_commit();

        const signed char* A = reinterpret_cast<const signed char*>(sm + buf * STAGE_BYTES);
        const signed char* B = reinterpret_cast<const signed char*>(sm + buf * STAGE_BYTES + STAGE_A);

        wmma::fragment<wmma::matrix_b, 16, 16, 16, signed char, wmma::col_major> bf[2][4];
        wmma::fragment<wmma::matrix_a, 16, 16, 16, signed char, wmma::row_major> af[2][2];
#pragma unroll
        for (int nt = 0; nt < 4; nt++)
            wmma::load_matrix_sync(bf[0][nt], B + (warp_n * 64 + nt * 16) * KSTR, KSTR);
#pragma unroll
        for (int mt = 0; mt < 2; mt++)
            wmma::load_matrix_sync(af[0][mt], A + (warp_m * 32 + mt * 16) * KSTR, KSTR);

#pragma unroll
        for (int ks = 0; ks < BK; ks += 16) {
            const int cur = (ks >> 4) & 1, nxt = cur ^ 1;
            if (ks + 16 < BK) {
#pragma unroll
                for (int nt = 0; nt < 4; nt++)
                    wmma::load_matrix_sync(bf[nxt][nt],
                        B + (warp_n * 64 + nt * 16) * KSTR + ks + 16, KSTR);
#pragma unroll
                for (int mt = 0; mt < 2; mt++)
                    wmma::load_matrix_sync(af[nxt][mt],
                        A + (warp_m * 32 + mt * 16) * KSTR + ks + 16, KSTR);
            }
#pragma unroll
            for (int mt = 0; mt < 2; mt++)
#pragma unroll
                for (int nt = 0; nt < 4; nt++)
                    wmma::mma_sync(acc[mt][nt], af[cur][mt], bf[cur][nt], acc[mt][nt]);
        }
    }
    __syncthreads();

    int* scr = reinterpret_cast<int*>(sm) + wid * (16 * 20);
    const int row = lane >> 1, half = lane & 1;
#pragma unroll
    for (int mt = 0; mt < 2; mt++) {
        float rs = 0.f;
        const float sa_t = sa_s[warp_m * 32 + mt * 16 + row] * INV_T;
#pragma unroll
        for (int nt = 0; nt < 4; nt++) {
            __syncwarp();
            wmma::store_matrix_sync(scr, acc[mt][nt], 20, wmma::mem_row_major);
            __syncwarp();
            const int* rp = scr + row * 20 + half * 8;
            const int cb = warp_n * 64 + nt * 16 + half * 8;
#pragma unroll
            for (int i = 0; i < 8; i++) {
                float dv = (float)rp[i] * sb_s[cb + i];
                rs += __expf(fmaf(dv, sa_t, -INV_T));
            }
        }
        rs += __shfl_xor_sync(0xffffffffu, rs, 1);
        if (half == 0)
            red[(warp_m * 32 + mt * 16 + row) * 2 + warp_n] = rs;
    }
    __syncthreads();
    if (tid < BM)
        g_part[blockIdx.y][p0 + tid] = red[tid * 2 + 0] + red[tid * 2 + 1];
}

// ---------------------------------------------------------------------------
// 4) Reduce + final. Blocks 0..15: unique-position LSE (coalesced, weighted
//    by multiplicity) + posdot sums. Blocks 16..47: neg sums. Ticket ends.
// ---------------------------------------------------------------------------
__global__ void reduce_final_kernel(float* __restrict__ out, int out_size) {
    const int b = blockIdx.x, t = threadIdx.x;
    double v0 = 0.0, v1 = 0.0, v2 = 0.0;
    if (b < 16) {
        const int idx = b * 256 + t;
        if (idx < g_count[0]) {
            float es = 0.f;
#pragma unroll
            for (int c = 0; c < NNT; c++) es += g_part[c][idx];   // coalesced
            v0 = (double)g_mult_pos[idx] * (double)logf(es);
        }
        v1 = (double)g_posdot[idx];
    } else {
        const int q = (b - 16) * 512 + t;
        v2 = (double)g_negdot[q] + (double)g_negdot[q + 256];
    }
    v0 = warp_sum_d(v0); v1 = warp_sum_d(v1); v2 = warp_sum_d(v2);
    __shared__ double sh[3][8];
    __shared__ bool is_last;
    if ((t & 31) == 0) { sh[0][t >> 5] = v0; sh[1][t >> 5] = v1; sh[2][t >> 5] = v2; }
    __syncthreads();
    if (t == 0) {
        double a = 0, bb = 0, c = 0;
#pragma unroll
        for (int i = 0; i < 8; i++) { a += sh[0][i]; bb += sh[1][i]; c += sh[2][i]; }
        g_red[b][0] = a; g_red[b][1] = bb; g_red[b][2] = c;
        __threadfence();
        is_last = (atomicAdd(&g_ctr, 1) == 47);
    }
    __syncthreads();
    if (is_last) {
        if (t == 0) {
            volatile double* gr = &g_red[0][0];
            double L0 = 0, P = 0, Ng = 0;
            for (int i = 0; i < 48; i++) {
                L0 += gr[i * 3 + 0]; P += gr[i * 3 + 1]; Ng += gr[i * 3 + 2];
            }
            out[0] = (float)((L0 - INV_T_D * P) / N_POS + INV_T_D);
            out[1] = (float)(P / N_POS);
            out[2] = (float)(Ng / N_NEG);
        }
        for (int i = 3 + t; i < out_size; i += 256) out[i] = 0.f;
    }
}

// ---------------------------------------------------------------------------
extern "C" void kernel_launch(void* const* d_in, const int* in_sizes, int n_in,
                              void* d_out, int out_size) {
    const float* emb = (const float*)d_in[0];
    const int* pa = (const int*)d_in[1];
    const int* pt = (const int*)d_in[2];
    const int* na = (const int*)d_in[3];
    const int* nt = (const int*)d_in[4];
    float* out = (float*)d_out;
    (void)in_sizes; (void)n_in;

    cudaFuncSetAttribute(lse_gemm_fused,
                         cudaFuncAttributeMaxDynamicSharedMemorySize, SMEM_TOTAL);

    dedup_kernel<<<1, 1024>>>(pa);
    normalize_kernel<<<N_EMB, 128>>>(emb);

    dim3 grid(NMT + 2, NNT);   // +2 block-columns = 128 pair-dot blocks
    lse_gemm_fused<<<grid, 256, SMEM_TOTAL>>>(pa, pt, na, nt);

    reduce_final_kernel<<<48, 256>>>(out, out_size);
}